// round 2
// baseline (speedup 1.0000x reference)
#include <cuda_runtime.h>
#include <cuda_bf16.h>

typedef unsigned long long u64;

#define BMAX 256

// scratch
__device__ float g_p1t  [BMAX * 14 * 14 * 32];   // (b, h, w, c) channel-last
__device__ float g_off2t[BMAX * 14 * 14 * 18];   // (b, h, w, c) channel-last
__device__ u64   g_w2d  [288 * 64];              // [k=kk*32+ci][o], each entry {w,w} packed
__device__ float g_ow2t [9 * 32 * 18];           // [tt][ci][c]
__device__ float g_p2   [BMAX * 64 * 7 * 7];     // (b, c, h, w)

// ---- packed f32x2 helpers (Blackwell) --------------------------------------
__device__ __forceinline__ u64 f2pack(float lo, float hi) {
    u64 r; asm("mov.b64 %0, {%1, %2};" : "=l"(r) : "f"(lo), "f"(hi)); return r;
}
__device__ __forceinline__ void f2unpack(u64 v, float& lo, float& hi) {
    asm("mov.b64 {%0, %1}, %2;" : "=f"(lo), "=f"(hi) : "l"(v));
}
__device__ __forceinline__ u64 fma2(u64 a, u64 b, u64 c) {
    u64 d; asm("fma.rn.f32x2 %0, %1, %2, %3;" : "=l"(d) : "l"(a), "l"(b), "l"(c));
    return d;
}

// bilinear corner sample, zero padding semantics
__device__ __forceinline__ float corner(const float* __restrict__ p,
                                        int y, int x, int H, int W, int stride) {
    bool v = (y >= 0) & (y < H) & (x >= 0) & (x < W);
    int yc = min(max(y, 0), H - 1);
    int xc = min(max(x, 0), W - 1);
    return v ? p[(yc * W + xc) * stride] : 0.f;
}

// ---------------------------------------------------------------------------
// Kernel 1: fused offset-conv(1->18) + deform-conv(1->32) + relu + maxpool2,
// plus weight-prep in trailing blocks (w2 dup-transpose, off_w2 transpose).
// ---------------------------------------------------------------------------
__global__ void __launch_bounds__(128)
k_stage1(const float* __restrict__ x,
         const float* __restrict__ ow, const float* __restrict__ ob,
         const float* __restrict__ w1, const float* __restrict__ b1,
         const float* __restrict__ off_w2, const float* __restrict__ w2,
         int B, int nb1) {
    if (blockIdx.x >= nb1) {
        // weight prep
        int i = (blockIdx.x - nb1) * 128 + threadIdx.x;
        if (i < 288 * 64) {
            int o = i / 288, r = i - o * 288, ci = r / 9, kk = r - ci * 9;
            float w = w2[i];
            g_w2d[(kk * 32 + ci) * 64 + o] = f2pack(w, w);
        } else {
            int j = i - 288 * 64;
            if (j < 18 * 32 * 9) {
                int c = j / 288, r = j - c * 288, ci = r / 9, tt = r - ci * 9;
                g_ow2t[(tt * 32 + ci) * 18 + c] = off_w2[j];
            }
        }
        return;
    }

    int idx = blockIdx.x * blockDim.x + threadIdx.x;
    if (idx >= B * 14 * 14) return;
    int w2i = idx % 14;
    int t   = idx / 14;
    int h2i = t % 14;
    int b   = t / 14;
    const float* xb = x + b * 784;

    float xp[4][9];
#pragma unroll
    for (int p = 0; p < 4; p++) {
        int h = h2i * 2 + (p >> 1), w = w2i * 2 + (p & 1);
#pragma unroll
        for (int tt = 0; tt < 9; tt++) {
            int yy = h + tt / 3 - 1, xx = w + tt % 3 - 1;
            xp[p][tt] = (yy >= 0 && yy < 28 && xx >= 0 && xx < 28) ? xb[yy * 28 + xx] : 0.f;
        }
    }

    float samp[4][9];
#pragma unroll
    for (int kk = 0; kk < 9; kk++) {
        float wr0[9], wr1[9];
#pragma unroll
        for (int tt = 0; tt < 9; tt++) {
            wr0[tt] = ow[(2 * kk) * 9 + tt];
            wr1[tt] = ow[(2 * kk + 1) * 9 + tt];
        }
        float bdy = ob[2 * kk], bdx = ob[2 * kk + 1];
        int iy = kk / 3 - 1, ix = kk % 3 - 1;
#pragma unroll
        for (int p = 0; p < 4; p++) {
            float dy = bdy, dx = bdx;
#pragma unroll
            for (int tt = 0; tt < 9; tt++) {
                dy = fmaf(wr0[tt], xp[p][tt], dy);
                dx = fmaf(wr1[tt], xp[p][tt], dx);
            }
            int h = h2i * 2 + (p >> 1), w = w2i * 2 + (p & 1);
            float py = (float)(h + iy) + dy;
            float px = (float)(w + ix) + dx;
            float fy = floorf(py), fx = floorf(px);
            float ay = py - fy, ax = px - fx;
            int y0 = (int)fy, x0 = (int)fx;
            float v00 = corner(xb, y0,     x0,     28, 28, 1);
            float v01 = corner(xb, y0,     x0 + 1, 28, 28, 1);
            float v10 = corner(xb, y0 + 1, x0,     28, 28, 1);
            float v11 = corner(xb, y0 + 1, x0 + 1, 28, 28, 1);
            samp[p][kk] = (1.f - ay) * ((1.f - ax) * v00 + ax * v01)
                        +         ay * ((1.f - ax) * v10 + ax * v11);
        }
    }

    float* o = g_p1t + (b * 196 + h2i * 14 + w2i) * 32;
#pragma unroll
    for (int oc = 0; oc < 32; oc++) {
        float wv[9];
#pragma unroll
        for (int kk = 0; kk < 9; kk++) wv[kk] = w1[oc * 9 + kk];
        float m = -1e30f;
#pragma unroll
        for (int p = 0; p < 4; p++) {
            float a = b1[oc];
#pragma unroll
            for (int kk = 0; kk < 9; kk++) a = fmaf(wv[kk], samp[p][kk], a);
            m = fmaxf(m, a);
        }
        o[oc] = fmaxf(m, 0.f);
    }
}

// ---------------------------------------------------------------------------
// Kernel 2: offset conv 2 (32->18, 14x14, pad 1). One thread per 2x2 pixel
// group (4-way weight reuse), f32x2 accumulators along output-channel pairs,
// weights from transposed g_ow2t [tt][ci][c] (c contiguous -> u64 pair loads).
// ---------------------------------------------------------------------------
__global__ void
k_offconv2(const float* __restrict__ obv, int B) {
    int idx = blockIdx.x * blockDim.x + threadIdx.x;
    if (idx >= B * 49) return;
    int g = idx % 49, b = idx / 49;
    int h0 = (g / 7) * 2, w0 = (g % 7) * 2;

    u64 acc[4][9];
#pragma unroll
    for (int cp = 0; cp < 9; cp++) {
        u64 bb = f2pack(obv[2 * cp], obv[2 * cp + 1]);
        acc[0][cp] = bb; acc[1][cp] = bb; acc[2][cp] = bb; acc[3][cp] = bb;
    }

    const float* pb = g_p1t + b * 6272;

    for (int tt = 0; tt < 9; tt++) {   // NOT unrolled: keep I-footprint sane
        int dy = tt / 3 - 1, dx = tt - (tt / 3) * 3 - 1;
        const float* wbase = g_ow2t + tt * 32 * 18;
#pragma unroll
        for (int cib = 0; cib < 4; cib++) {
            float v[4][8];
#pragma unroll
            for (int pix = 0; pix < 4; pix++) {
                int y  = h0 + (pix >> 1) + dy;
                int xx = w0 + (pix & 1) + dx;
                bool ok = (y >= 0) & (y < 14) & (xx >= 0) & (xx < 14);
                const float* p = pb + (y * 14 + xx) * 32 + cib * 8;
                float4 a  = ok ? *(const float4*)p       : make_float4(0, 0, 0, 0);
                float4 c4 = ok ? *(const float4*)(p + 4) : make_float4(0, 0, 0, 0);
                v[pix][0] = a.x;  v[pix][1] = a.y;  v[pix][2] = a.z;  v[pix][3] = a.w;
                v[pix][4] = c4.x; v[pix][5] = c4.y; v[pix][6] = c4.z; v[pix][7] = c4.w;
            }
#pragma unroll
            for (int q = 0; q < 8; q++) {
                const u64* wp = (const u64*)(wbase + (cib * 8 + q) * 18);
                u64 wr[9];
#pragma unroll
                for (int cp = 0; cp < 9; cp++) wr[cp] = wp[cp];
#pragma unroll
                for (int pix = 0; pix < 4; pix++) {
                    u64 vd = f2pack(v[pix][q], v[pix][q]);
#pragma unroll
                    for (int cp = 0; cp < 9; cp++)
                        acc[pix][cp] = fma2(vd, wr[cp], acc[pix][cp]);
                }
            }
        }
    }

#pragma unroll
    for (int pix = 0; pix < 4; pix++) {
        float* o = g_off2t + ((b * 196 + (h0 + (pix >> 1)) * 14 + (w0 + (pix & 1))) * 18);
#pragma unroll
        for (int cp = 0; cp < 9; cp++) *(u64*)(o + 2 * cp) = acc[pix][cp];
    }
}

// ---------------------------------------------------------------------------
// Kernel 4: deform conv 2 (K=288 -> N=64) + relu + maxpool2, register-tiled.
// Block = 8 pooled pixels (M=32 quadrant rows), 64 threads.
// Phase 1: stage samples in SMEM [k][34] (lane=channel -> coalesced gathers,
//          STS 2-way conflict only; LDS.64 pairs conflict-free & aligned).
// Phase 2: thread (tm,tn) computes 4(m) x 8(n) tile via f32x2 FMAs:
//          2 LDS.64 + 4 LDG.128 + 16 FMA2 per k  (32 FMAs / 22 instr).
// ---------------------------------------------------------------------------
__global__ void __launch_bounds__(64)
k_deform2(const float* __restrict__ b2, int B) {
    __shared__ float samp[288][34];
    int tid  = threadIdx.x;
    int pix0 = blockIdx.x * 8;
    int npix = B * 49;

    // ---- phase 1: 8 pix * 4 quad * 288 = 9216 bilinear samples ----
#pragma unroll 2
    for (int i = 0; i < 144; i++) {
        int e  = i * 64 + tid;
        int m  = e / 288;               // 0..31 (warp-uniform)
        int r  = e - m * 288;
        int kk = r >> 5;                // warp-uniform
        int ci = r & 31;                // = lane -> coalesced
        int pix = pix0 + (m >> 2);
        int q   = m & 3;
        float val = 0.f;
        if (pix < npix) {
            int b  = pix / 49;
            int s  = pix - b * 49;
            int h3 = s / 7, w3 = s - h3 * 7;
            int h  = h3 * 2 + (q >> 1), w = w3 * 2 + (q & 1);
            const float* od = g_off2t + (b * 196 + h * 14 + w) * 18 + 2 * kk;
            float dy = od[0], dx = od[1];
            int iy = kk / 3;
            float py = (float)(h + iy - 1) + dy;
            float px = (float)(w + (kk - iy * 3) - 1) + dx;
            float fy = floorf(py), fx = floorf(px);
            float ay = py - fy, ax = px - fx;
            int y0 = (int)fy, x0 = (int)fx;
            const float* pc = g_p1t + b * 6272 + ci;
            float v00 = corner(pc, y0,     x0,     14, 14, 32);
            float v01 = corner(pc, y0,     x0 + 1, 14, 14, 32);
            float v10 = corner(pc, y0 + 1, x0,     14, 14, 32);
            float v11 = corner(pc, y0 + 1, x0 + 1, 14, 14, 32);
            val = (1.f - ay) * ((1.f - ax) * v00 + ax * v01)
                +         ay * ((1.f - ax) * v10 + ax * v11);
        }
        samp[kk * 32 + ci][m] = val;
    }
    __syncthreads();

    // ---- phase 2: 32x64x288 GEMM, 4x8 tile per thread, f32x2 ----
    int tn = tid & 7, tm = tid >> 3;    // warp0 = tm 0..3 (LDS conflict-free)
    u64 acc[2][8];
#pragma unroll
    for (int j = 0; j < 2; j++)
#pragma unroll
        for (int nl = 0; nl < 8; nl++) acc[j][nl] = 0ULL;

    const u64*  wbase = g_w2d + tn * 8;
    const float* srow = &samp[0][4 * tm];

#pragma unroll 4
    for (int k = 0; k < 288; k++) {
        u64 s0 = *(const u64*)(srow + k * 34);
        u64 s1 = *(const u64*)(srow + k * 34 + 2);
        const u64* wk = wbase + k * 64;
        ulonglong2 wa = *(const ulonglong2*)(wk);
        ulonglong2 wb = *(const ulonglong2*)(wk + 2);
        ulonglong2 wc = *(const ulonglong2*)(wk + 4);
        ulonglong2 wd = *(const ulonglong2*)(wk + 6);
        u64 wv[8] = {wa.x, wa.y, wb.x, wb.y, wc.x, wc.y, wd.x, wd.y};
#pragma unroll
        for (int nl = 0; nl < 8; nl++) {
            acc[0][nl] = fma2(s0, wv[nl], acc[0][nl]);
            acc[1][nl] = fma2(s1, wv[nl], acc[1][nl]);
        }
    }

    // ---- epilogue: pool(max of 4 quadrants) + bias + relu ----
    int pix = pix0 + tm;                // thread tm owns pixel tm entirely
    if (pix < npix) {
        int b = pix / 49, s = pix - b * 49;
        int h3 = s / 7, w3 = s - h3 * 7;
        float* o = g_p2 + b * 3136 + h3 * 7 + w3;
#pragma unroll
        for (int nl = 0; nl < 8; nl++) {
            int n = tn * 8 + nl;
            float a, bq, c, d;
            f2unpack(acc[0][nl], a, bq);
            f2unpack(acc[1][nl], c, d);
            float mx = fmaxf(fmaxf(a, bq), fmaxf(c, d));
            o[n * 49] = fmaxf(mx + b2[n], 0.f);
        }
    }
}

// ---------------------------------------------------------------------------
// Kernel 5: FC (B,3136) @ (10,3136)^T + bias. One warp per (b, oc).
// ---------------------------------------------------------------------------
__global__ void __launch_bounds__(320)
k_fc(const float* __restrict__ fw, const float* __restrict__ fb,
     float* __restrict__ out, int B) {
    int b = blockIdx.x;
    int warp = threadIdx.x >> 5;
    int lane = threadIdx.x & 31;
    const float* row = g_p2 + b * 3136;
    const float* wr  = fw + warp * 3136;
    float s = 0.f;
    for (int i = lane * 4; i < 3136; i += 128) {
        float4 a = *(const float4*)(row + i);
        float4 w = *(const float4*)(wr + i);
        s += a.x * w.x + a.y * w.y + a.z * w.z + a.w * w.w;
    }
#pragma unroll
    for (int off = 16; off; off >>= 1) s += __shfl_xor_sync(0xffffffffu, s, off);
    if (lane == 0) out[b * 10 + warp] = s + fb[warp];
}

// ---------------------------------------------------------------------------
extern "C" void kernel_launch(void* const* d_in, const int* in_sizes, int n_in,
                              void* d_out, int out_size) {
    const float* x      = (const float*)d_in[0];
    const float* off_w1 = (const float*)d_in[1];
    const float* off_b1 = (const float*)d_in[2];
    const float* w1     = (const float*)d_in[3];
    const float* b1     = (const float*)d_in[4];
    const float* off_w2 = (const float*)d_in[5];
    const float* off_b2 = (const float*)d_in[6];
    const float* w2     = (const float*)d_in[7];
    const float* b2     = (const float*)d_in[8];
    const float* fc_w   = (const float*)d_in[9];
    const float* fc_b   = (const float*)d_in[10];
    float* out = (float*)d_out;

    int B = in_sizes[0] / 784;
    if (B > BMAX) B = BMAX;

    int nb1   = (B * 196 + 127) / 128;
    int nprep = (288 * 64 + 18 * 32 * 9 + 127) / 128;

    k_stage1<<<nb1 + nprep, 128>>>(x, off_w1, off_b1, w1, b1, off_w2, w2, B, nb1);
    k_offconv2<<<(B * 49 + 127) / 128, 128>>>(off_b2, B);
    k_deform2<<<(B * 49 + 7) / 8, 64>>>(b2, B);
    k_fc<<<B, 320>>>(fc_w, fc_b, out, B);
}

// round 4
// speedup vs baseline: 2.0275x; 2.0275x over previous
#include <cuda_runtime.h>
#include <cuda_bf16.h>

#define BMAX 256

// scratch (channel-last where noted)
__device__ float g_p1t  [BMAX * 14 * 14 * 32];   // (b, h, w, c)
__device__ float g_off2t[BMAX * 14 * 14 * 18];   // (b, h, w, c)
__device__ float g_w2t  [288 * 64];              // [kk*32+ci][o]
__device__ float g_p2   [BMAX * 64 * 7 * 7];     // (b, c, h, w)

// bilinear corner sample, zero padding semantics
__device__ __forceinline__ float corner(const float* __restrict__ p,
                                        int y, int x, int H, int W, int stride) {
    bool v = (y >= 0) & (y < H) & (x >= 0) & (x < W);
    int yc = min(max(y, 0), H - 1);
    int xc = min(max(x, 0), W - 1);
    return v ? p[(yc * W + xc) * stride] : 0.f;
}

// ---------------------------------------------------------------------------
// Kernel 1: fused offset-conv(1->18) + deform-conv(1->32) + relu + maxpool2.
// One thread per pooled output pixel (b, h2, w2); computes 4 input pixels.
// Writes p1 channel-last.
// ---------------------------------------------------------------------------
__global__ void __launch_bounds__(128)
k_stage1(const float* __restrict__ x,
         const float* __restrict__ ow, const float* __restrict__ ob,
         const float* __restrict__ w1, const float* __restrict__ b1, int B) {
    int idx = blockIdx.x * blockDim.x + threadIdx.x;
    if (idx >= B * 14 * 14) return;
    int w2i = idx % 14;
    int t   = idx / 14;
    int h2i = t % 14;
    int b   = t / 14;
    const float* xb = x + b * 784;

    float xp[4][9];
#pragma unroll
    for (int p = 0; p < 4; p++) {
        int h = h2i * 2 + (p >> 1), w = w2i * 2 + (p & 1);
#pragma unroll
        for (int tt = 0; tt < 9; tt++) {
            int yy = h + tt / 3 - 1, xx = w + tt % 3 - 1;
            xp[p][tt] = (yy >= 0 && yy < 28 && xx >= 0 && xx < 28) ? xb[yy * 28 + xx] : 0.f;
        }
    }

    float samp[4][9];
#pragma unroll
    for (int kk = 0; kk < 9; kk++) {
        float wr0[9], wr1[9];
#pragma unroll
        for (int tt = 0; tt < 9; tt++) {
            wr0[tt] = ow[(2 * kk) * 9 + tt];
            wr1[tt] = ow[(2 * kk + 1) * 9 + tt];
        }
        float bdy = ob[2 * kk], bdx = ob[2 * kk + 1];
        int iy = kk / 3 - 1, ix = kk % 3 - 1;
#pragma unroll
        for (int p = 0; p < 4; p++) {
            float dy = bdy, dx = bdx;
#pragma unroll
            for (int tt = 0; tt < 9; tt++) {
                dy = fmaf(wr0[tt], xp[p][tt], dy);
                dx = fmaf(wr1[tt], xp[p][tt], dx);
            }
            int h = h2i * 2 + (p >> 1), w = w2i * 2 + (p & 1);
            float py = (float)(h + iy) + dy;
            float px = (float)(w + ix) + dx;
            float fy = floorf(py), fx = floorf(px);
            float ay = py - fy, ax = px - fx;
            int y0 = (int)fy, x0 = (int)fx;
            float v00 = corner(xb, y0,     x0,     28, 28, 1);
            float v01 = corner(xb, y0,     x0 + 1, 28, 28, 1);
            float v10 = corner(xb, y0 + 1, x0,     28, 28, 1);
            float v11 = corner(xb, y0 + 1, x0 + 1, 28, 28, 1);
            samp[p][kk] = (1.f - ay) * ((1.f - ax) * v00 + ax * v01)
                        +         ay * ((1.f - ax) * v10 + ax * v11);
        }
    }

    float* o = g_p1t + (b * 196 + h2i * 14 + w2i) * 32;
#pragma unroll
    for (int oc = 0; oc < 32; oc++) {
        float wv[9];
#pragma unroll
        for (int kk = 0; kk < 9; kk++) wv[kk] = w1[oc * 9 + kk];
        float m = -1e30f;
#pragma unroll
        for (int p = 0; p < 4; p++) {
            float a = b1[oc];
#pragma unroll
            for (int kk = 0; kk < 9; kk++) a = fmaf(wv[kk], samp[p][kk], a);
            m = fmaxf(m, a);
        }
        o[oc] = fmaxf(m, 0.f);
    }
}

// ---------------------------------------------------------------------------
// Kernel 2: offset conv 2 (32 -> 18 channels, 14x14, pad 1).
// One thread per pixel PAIR along w (2 pixels share every weight load).
// ---------------------------------------------------------------------------
__global__ void __launch_bounds__(128)
k_offconv2(const float* __restrict__ ow, const float* __restrict__ ob, int B) {
    int idx = blockIdx.x * blockDim.x + threadIdx.x;
    if (idx >= B * 14 * 7) return;
    int wp = idx % 7;
    int t  = idx / 7;
    int h  = t % 14;
    int b  = t / 14;
    int w0 = wp * 2;

    float acc[2][18];
#pragma unroll
    for (int c = 0; c < 18; c++) { acc[0][c] = ob[c]; acc[1][c] = ob[c]; }

    const float* pb = g_p1t + b * 196 * 32;

    for (int tt = 0; tt < 9; tt++) {
        int y  = h + tt / 3 - 1;
        int dx = tt % 3 - 1;
        int x0 = w0 + dx, x1 = w0 + 1 + dx;
        bool yok = (y >= 0) & (y < 14);
        bool ok0 = yok & (x0 >= 0) & (x0 < 14);
        bool ok1 = yok & (x1 >= 0) & (x1 < 14);
        const float* p0 = pb + (y * 14 + x0) * 32;
        const float* p1 = pb + (y * 14 + x1) * 32;

        for (int cib = 0; cib < 4; cib++) {
            float v0[8], v1[8];
            if (ok0) {
                float4 a = *(const float4*)(p0 + cib * 8);
                float4 c4 = *(const float4*)(p0 + cib * 8 + 4);
                v0[0] = a.x; v0[1] = a.y; v0[2] = a.z; v0[3] = a.w;
                v0[4] = c4.x; v0[5] = c4.y; v0[6] = c4.z; v0[7] = c4.w;
            } else {
#pragma unroll
                for (int q = 0; q < 8; q++) v0[q] = 0.f;
            }
            if (ok1) {
                float4 a = *(const float4*)(p1 + cib * 8);
                float4 c4 = *(const float4*)(p1 + cib * 8 + 4);
                v1[0] = a.x; v1[1] = a.y; v1[2] = a.z; v1[3] = a.w;
                v1[4] = c4.x; v1[5] = c4.y; v1[6] = c4.z; v1[7] = c4.w;
            } else {
#pragma unroll
                for (int q = 0; q < 8; q++) v1[q] = 0.f;
            }
#pragma unroll
            for (int c = 0; c < 18; c++) {
#pragma unroll
                for (int q = 0; q < 8; q++) {
                    float wv = ow[(c * 32 + cib * 8 + q) * 9 + tt];
                    acc[0][c] = fmaf(wv, v0[q], acc[0][c]);
                    acc[1][c] = fmaf(wv, v1[q], acc[1][c]);
                }
            }
        }
    }

    float* o = g_off2t + (b * 196 + h * 14 + w0) * 18;
#pragma unroll
    for (int c = 0; c < 18; c++) { o[c] = acc[0][c]; o[18 + c] = acc[1][c]; }
}

// ---------------------------------------------------------------------------
// Kernel 3: transpose w2 (64,32,3,3) -> [kk*32+ci][o]
// ---------------------------------------------------------------------------
__global__ void k_transpose_w2(const float* __restrict__ w2) {
    int i = blockIdx.x * blockDim.x + threadIdx.x;
    if (i >= 64 * 288) return;
    int o = i / 288, r = i % 288, ci = r / 9, kk = r % 9;
    g_w2t[(kk * 32 + ci) * 64 + o] = w2[i];
}

// ---------------------------------------------------------------------------
// Kernel 4: deform conv 2 (K=288 -> N=64) + relu + maxpool2.
// Block = TWO pooled output pixels, 64 threads.
// Phase 1: stage bilinear samples in SMEM layout samp[pix][k][4]
//          (lane = channel -> coalesced gathers; quadrants contiguous).
// Phase 2: thread o = output channel; per k:
//          1 coalesced weight LDG + 2 broadcast LDS.128 + 8 FMA
//          (1.375 issue slots per FMA vs 2.25 in the 1-pixel version).
// ---------------------------------------------------------------------------
__global__ void __launch_bounds__(64)
k_deform2(const float* __restrict__ b2, int B) {
    __shared__ float samp[2][288][4];          // 9216 B
    int tid  = threadIdx.x;
    int pix0 = blockIdx.x * 2;
    int npix = B * 49;

    // ---- phase 1: 2 pix * 4 quad * 288 = 2304 samples, 36 iters ----
#pragma unroll 2
    for (int i = 0; i < 36; i++) {
        int e  = i * 64 + tid;
        int ci = e & 31;                 // lane -> coalesced gathers
        int u  = e >> 5;                 // 0..71, warp-uniform
        int kk = u % 9;
        int v  = u / 9;                  // 0..7
        int p  = v & 3;
        int pl = v >> 2;                 // pixel-local 0..1
        int pix = pix0 + pl;
        float val = 0.f;
        if (pix < npix) {
            int b  = pix / 49;
            int s  = pix - b * 49;
            int h3 = s / 7, w3 = s - h3 * 7;
            int h  = h3 * 2 + (p >> 1), w = w3 * 2 + (p & 1);
            const float* od = g_off2t + (b * 196 + h * 14 + w) * 18 + 2 * kk;
            float dy = od[0], dx = od[1];
            int iy = kk / 3;
            float py = (float)(h + iy - 1) + dy;
            float px = (float)(w + (kk - iy * 3) - 1) + dx;
            float fy = floorf(py), fx = floorf(px);
            float ay = py - fy, ax = px - fx;
            int y0 = (int)fy, x0 = (int)fx;
            const float* pc = g_p1t + b * 6272 + ci;
            float v00 = corner(pc, y0,     x0,     14, 14, 32);
            float v01 = corner(pc, y0,     x0 + 1, 14, 14, 32);
            float v10 = corner(pc, y0 + 1, x0,     14, 14, 32);
            float v11 = corner(pc, y0 + 1, x0 + 1, 14, 14, 32);
            val = (1.f - ay) * ((1.f - ax) * v00 + ax * v01)
                +         ay * ((1.f - ax) * v10 + ax * v11);
        }
        samp[pl][kk * 32 + ci][p] = val;
    }
    __syncthreads();

    // ---- phase 2: thread = output channel o ----
    int o = tid;
    float a0[4] = {0.f, 0.f, 0.f, 0.f};
    float a1[4] = {0.f, 0.f, 0.f, 0.f};
    const float* wt = g_w2t + o;

#pragma unroll 4
    for (int k = 0; k < 288; k++) {
        float wv = wt[k * 64];                       // coalesced, L1-resident
        float4 s0 = *(const float4*)samp[0][k];      // broadcast LDS.128
        float4 s1 = *(const float4*)samp[1][k];      // broadcast LDS.128
        a0[0] = fmaf(wv, s0.x, a0[0]);
        a0[1] = fmaf(wv, s0.y, a0[1]);
        a0[2] = fmaf(wv, s0.z, a0[2]);
        a0[3] = fmaf(wv, s0.w, a0[3]);
        a1[0] = fmaf(wv, s1.x, a1[0]);
        a1[1] = fmaf(wv, s1.y, a1[1]);
        a1[2] = fmaf(wv, s1.z, a1[2]);
        a1[3] = fmaf(wv, s1.w, a1[3]);
    }

    // ---- epilogue: pool(max of 4 quadrants) + bias + relu ----
    float bias = b2[o];
#pragma unroll
    for (int pl = 0; pl < 2; pl++) {
        int pix = pix0 + pl;
        if (pix < npix) {
            int b = pix / 49, s = pix - b * 49;
            int h3 = s / 7, w3 = s - h3 * 7;
            float* acc = pl ? a1 : a0;
            float m = fmaxf(fmaxf(acc[0], acc[1]), fmaxf(acc[2], acc[3]));
            g_p2[(b * 64 + o) * 49 + h3 * 7 + w3] = fmaxf(m + bias, 0.f);
        }
    }
}

// ---------------------------------------------------------------------------
// Kernel 5: FC (B,3136) @ (10,3136)^T + bias. One warp per (b, oc),
// unrolled for memory-level parallelism.
// ---------------------------------------------------------------------------
__global__ void __launch_bounds__(320)
k_fc(const float* __restrict__ fw, const float* __restrict__ fb,
     float* __restrict__ out, int B) {
    int b = blockIdx.x;
    int warp = threadIdx.x >> 5;
    int lane = threadIdx.x & 31;
    const float* row = g_p2 + b * 3136;
    const float* wr  = fw + warp * 3136;
    float s = 0.f;
    int i = lane * 4;
#pragma unroll 4
    for (int it = 0; it < 24; it++, i += 128) {
        float4 a = *(const float4*)(row + i);
        float4 w = *(const float4*)(wr + i);
        s = fmaf(a.x, w.x, s); s = fmaf(a.y, w.y, s);
        s = fmaf(a.z, w.z, s); s = fmaf(a.w, w.w, s);
    }
    if (i < 3136) {                      // tail: lanes 0..15
        float4 a = *(const float4*)(row + i);
        float4 w = *(const float4*)(wr + i);
        s = fmaf(a.x, w.x, s); s = fmaf(a.y, w.y, s);
        s = fmaf(a.z, w.z, s); s = fmaf(a.w, w.w, s);
    }
#pragma unroll
    for (int off = 16; off; off >>= 1) s += __shfl_xor_sync(0xffffffffu, s, off);
    if (lane == 0) out[b * 10 + warp] = s + fb[warp];
}

// ---------------------------------------------------------------------------
extern "C" void kernel_launch(void* const* d_in, const int* in_sizes, int n_in,
                              void* d_out, int out_size) {
    const float* x      = (const float*)d_in[0];
    const float* off_w1 = (const float*)d_in[1];
    const float* off_b1 = (const float*)d_in[2];
    const float* w1     = (const float*)d_in[3];
    const float* b1     = (const float*)d_in[4];
    const float* off_w2 = (const float*)d_in[5];
    const float* off_b2 = (const float*)d_in[6];
    const float* w2     = (const float*)d_in[7];
    const float* b2     = (const float*)d_in[8];
    const float* fc_w   = (const float*)d_in[9];
    const float* fc_b   = (const float*)d_in[10];
    float* out = (float*)d_out;

    int B = in_sizes[0] / 784;
    if (B > BMAX) B = BMAX;

    k_transpose_w2<<<(64 * 288 + 255) / 256, 256>>>(w2);
    k_stage1<<<(B * 196 + 127) / 128, 128>>>(x, off_w1, off_b1, w1, b1, B);
    k_offconv2<<<(B * 98 + 127) / 128, 128>>>(off_w2, off_b2, B);
    k_deform2<<<(B * 49 + 1) / 2, 64>>>(b2, B);
    k_fc<<<B, 320>>>(fc_w, fc_b, out, B);
}